// round 1
// baseline (speedup 1.0000x reference)
#include <cuda_runtime.h>
#include <math.h>

#define BB   128   // batch
#define SS   64    // steps
#define HH   128   // hidden H
#define WWID 256   // MLP width W
#define DD   136   // L-1
#define DIN  64
#define NBC  3
#define NCTA ((BB + NBC - 1) / NBC)   // 43

// ---------------- device scratch (allocation-free rule: __device__ globals) ----------
__device__ float g_G[(size_t)BB * SS * WWID * HH];   // 268,435,456 floats = 1 GiB
__device__ float g_cbias[BB * SS * HH];              // 4 MB
__device__ float g_h0[BB * HH];
__device__ float g_At[DD * BB * SS];                 // coeffs^T  [136][8192]
__device__ float g_Bt[DD * WWID * HH];               // ml_w^T    [136][32768]

// ---------------- packed fp32x2 FMA (Blackwell FFMA2) --------------------------------
__device__ __forceinline__ float2 fma2(float2 d, float2 a, float2 b) {
    union U { float2 f; unsigned long long u; };
    U ud, ua, ub; ud.f = d; ua.f = a; ub.f = b;
    asm("fma.rn.f32x2 %0, %1, %2, %0;" : "+l"(ud.u) : "l"(ua.u), "l"(ub.u));
    return ud.f;
}

// ---------------- h0 = initial @ in_w + in_b -----------------------------------------
__global__ void k_h0(const float* __restrict__ initial, const float* __restrict__ in_w,
                     const float* __restrict__ in_b, float* __restrict__ out, int write_feat) {
    int b = blockIdx.x, t = threadIdx.x;   // 128 threads = H
    __shared__ float si[DIN];
    if (t < DIN) si[t] = initial[b * DIN + t];
    __syncthreads();
    float acc = in_b[t];
    #pragma unroll 8
    for (int k = 0; k < DIN; ++k) acc = fmaf(si[k], in_w[k * HH + t], acc);
    g_h0[b * HH + t] = acc;
    if (write_feat) out[(size_t)b * (SS + 1) * HH + t] = acc;
}

// ---------------- tiled transpose: dest[c][R] = in[r*stride + off + c] ---------------
__global__ void k_transpose(const float* __restrict__ in, int R, int C, int stride,
                            int off, int dest) {
    __shared__ float tile[32][33];
    float* out = dest ? g_Bt : g_At;
    int c0 = blockIdx.x * 32, r0 = blockIdx.y * 32;
    int tx = threadIdx.x, ty = threadIdx.y;  // (32,8)
    for (int i = ty; i < 32; i += 8) {
        int r = r0 + i, c = c0 + tx;
        if (r < R && c < C) tile[i][tx] = in[(size_t)r * stride + off + c];
    }
    __syncthreads();
    for (int i = ty; i < 32; i += 8) {
        int c = c0 + i, r = r0 + tx;
        if (r < R && c < C) out[(size_t)c * R + r] = tile[tx][i];
    }
}

// ---------------- cbias[i][h] = sum_d ml_b[h*136+d] * coeffs[i][d] -------------------
__global__ void k_cbias(const float* __restrict__ logsig, const float* __restrict__ ml_b) {
    int i = blockIdx.x, t = threadIdx.x;   // i over 8192, 128 threads = H
    __shared__ float sA[DD];
    for (int d = t; d < DD; d += 128) sA[d] = logsig[(size_t)i * (DD + 1) + 1 + d];
    __syncthreads();
    float acc = 0.f;
    const float* mb = ml_b + (size_t)t * DD;
    #pragma unroll 8
    for (int d = 0; d < DD; ++d) acc = fmaf(sA[d], __ldg(&mb[d]), acc);
    g_cbias[(size_t)i * HH + t] = acc;
}

// ---------------- G GEMM: C[8192 x 32768] = At^T * Bt  (K = 136) ---------------------
__global__ void __launch_bounds__(256, 2) k_gemmG() {
    const int MI = BB * SS;        // 8192
    const int NJ = WWID * HH;      // 32768
    __shared__ float As[34][128];
    __shared__ float Bs[34][128];
    int j0 = blockIdx.x * 128;
    int i0 = blockIdx.y * 128;
    int t = threadIdx.x;
    int tx = t & 15, ty = t >> 4;
    float2 acc[8][4];
    #pragma unroll
    for (int r = 0; r < 8; ++r)
        #pragma unroll
        for (int c = 0; c < 4; ++c) acc[r][c] = make_float2(0.f, 0.f);

    for (int kc = 0; kc < 4; ++kc) {
        #pragma unroll
        for (int l = 0; l < 17; ++l) {
            int idx = t + l * 256;
            int kk = idx >> 7, ii = idx & 127;
            As[kk][ii] = g_At[(size_t)(kc * 34 + kk) * MI + i0 + ii];
            Bs[kk][ii] = g_Bt[(size_t)(kc * 34 + kk) * NJ + j0 + ii];
        }
        __syncthreads();
        #pragma unroll 2
        for (int kk = 0; kk < 34; ++kk) {
            float a[8], b[8];
            float4 a0 = *(const float4*)&As[kk][ty * 8];
            float4 a1 = *(const float4*)&As[kk][ty * 8 + 4];
            float4 b0 = *(const float4*)&Bs[kk][tx * 8];
            float4 b1 = *(const float4*)&Bs[kk][tx * 8 + 4];
            a[0]=a0.x; a[1]=a0.y; a[2]=a0.z; a[3]=a0.w; a[4]=a1.x; a[5]=a1.y; a[6]=a1.z; a[7]=a1.w;
            b[0]=b0.x; b[1]=b0.y; b[2]=b0.z; b[3]=b0.w; b[4]=b1.x; b[5]=b1.y; b[6]=b1.z; b[7]=b1.w;
            #pragma unroll
            for (int r = 0; r < 8; ++r) {
                float2 a2 = make_float2(a[r], a[r]);
                #pragma unroll
                for (int c = 0; c < 4; ++c)
                    acc[r][c] = fma2(acc[r][c], a2, make_float2(b[2*c], b[2*c+1]));
            }
        }
        __syncthreads();
    }
    #pragma unroll
    for (int r = 0; r < 8; ++r) {
        size_t row = (size_t)(i0 + ty * 8 + r) * NJ + j0 + tx * 8;
        float4 o0 = make_float4(acc[r][0].x, acc[r][0].y, acc[r][1].x, acc[r][1].y);
        float4 o1 = make_float4(acc[r][2].x, acc[r][2].y, acc[r][3].x, acc[r][3].y);
        *(float4*)&g_G[row]     = o0;
        *(float4*)&g_G[row + 4] = o1;
    }
}

// ---------------- scan kernel: 43 CTAs x 3 batch rows, 64 RK2 steps ------------------
// MLP stage: out[j][n] = act( bias[n] + sum_k in[j][k] * Wg[k][n] ),  n in [0,256)
template <int K, int ACT>
__device__ __forceinline__ void mlp_stage(const float* sIn, const float* __restrict__ Wg,
                                          const float* __restrict__ bias, float* sOut,
                                          float* sRed, int nb, int t) {
    const int Kc = K / 4;
    int kc = t >> 6, g = t & 63, n0 = g * 4;
    float2 axy[NBC], azw[NBC];
    #pragma unroll
    for (int j = 0; j < NBC; ++j) { axy[j] = make_float2(0.f, 0.f); azw[j] = make_float2(0.f, 0.f); }
    #pragma unroll 4
    for (int kk = 0; kk < Kc; ++kk) {
        int k = kc * Kc + kk;
        float4 w4 = __ldg((const float4*)(Wg + (size_t)k * WWID + n0));
        float2 wxy = make_float2(w4.x, w4.y), wzw = make_float2(w4.z, w4.w);
        #pragma unroll
        for (int j = 0; j < NBC; ++j) {
            if (j < nb) {
                float a = sIn[j * K + k];
                float2 a2 = make_float2(a, a);
                axy[j] = fma2(axy[j], a2, wxy);
                azw[j] = fma2(azw[j], a2, wzw);
            }
        }
    }
    #pragma unroll
    for (int j = 0; j < NBC; ++j)
        if (j < nb)
            *(float4*)&sRed[(kc * NBC + j) * 256 + n0] =
                make_float4(axy[j].x, axy[j].y, azw[j].x, azw[j].y);
    __syncthreads();
    if (t < 64 * NBC) {
        int j = t >> 6, gg = t & 63, m0 = gg * 4;
        if (j < nb) {
            float4 s = make_float4(0.f, 0.f, 0.f, 0.f);
            #pragma unroll
            for (int q = 0; q < 4; ++q) {
                float4 p = *(const float4*)&sRed[(q * NBC + j) * 256 + m0];
                s.x += p.x; s.y += p.y; s.z += p.z; s.w += p.w;
            }
            float4 bb = __ldg((const float4*)(bias + m0));
            s.x += bb.x; s.y += bb.y; s.z += bb.z; s.w += bb.w;
            if (ACT == 0) {
                s.x = fmaxf(s.x, 0.f); s.y = fmaxf(s.y, 0.f);
                s.z = fmaxf(s.z, 0.f); s.w = fmaxf(s.w, 0.f);
            } else {
                s.x = tanhf(s.x); s.y = tanhf(s.y); s.z = tanhf(s.z); s.w = tanhf(s.w);
            }
            *(float4*)&sOut[j * 256 + m0] = s;
        }
    }
    __syncthreads();
}

// contraction: sK[j][h] = cbias[b_j,m,h] + sum_w shv[j][w] * G[b_j,m,w,h]
__device__ __forceinline__ void contract_stage(const float* shv, int m, int b0, int nb,
                                               float* sK, float* sRed, int t) {
    int wq = t >> 5, hq = t & 31, h0 = hq * 4;
    float2 axy[NBC], azw[NBC];
    const float4* Gb[NBC];
    #pragma unroll
    for (int j = 0; j < NBC; ++j) {
        axy[j] = make_float2(0.f, 0.f); azw[j] = make_float2(0.f, 0.f);
        int b = (b0 + j < BB) ? (b0 + j) : (BB - 1);
        Gb[j] = (const float4*)(g_G + ((size_t)b * SS + m) * WWID * HH);
    }
    #pragma unroll 4
    for (int ww = 0; ww < 32; ++ww) {
        int w = wq * 32 + ww;
        #pragma unroll
        for (int j = 0; j < NBC; ++j) {
            if (j < nb) {
                float4 g4 = __ldg(&Gb[j][w * 32 + hq]);
                float a = shv[j * WWID + w];
                float2 a2 = make_float2(a, a);
                axy[j] = fma2(axy[j], a2, make_float2(g4.x, g4.y));
                azw[j] = fma2(azw[j], a2, make_float2(g4.z, g4.w));
            }
        }
    }
    #pragma unroll
    for (int j = 0; j < NBC; ++j)
        if (j < nb)
            *(float4*)&sRed[(wq * NBC + j) * 128 + h0] =
                make_float4(axy[j].x, axy[j].y, azw[j].x, azw[j].y);
    __syncthreads();
    if (t < HH) {
        #pragma unroll
        for (int j = 0; j < NBC; ++j) {
            if (j < nb) {
                float v = g_cbias[((size_t)(b0 + j) * SS + m) * HH + t];
                #pragma unroll
                for (int q = 0; q < 8; ++q) v += sRed[(q * NBC + j) * 128 + t];
                sK[j * HH + t] = v;
            }
        }
    }
    __syncthreads();
}

__global__ void __launch_bounds__(256, 1) k_scan(
        const float* __restrict__ h1_w, const float* __restrict__ h1_b,
        const float* __restrict__ h2_w, const float* __restrict__ h2_b,
        const float* __restrict__ vo_w, const float* __restrict__ vo_b,
        float* __restrict__ out, int write_feat, long long last_off) {
    __shared__ float sy[NBC * HH], sym[NBC * HH], sk1[NBC * HH], sk2[NBC * HH];
    __shared__ float sbA[NBC * WWID], sbB[NBC * WWID];
    __shared__ float sRed[4 * NBC * 256];
    int t = threadIdx.x;
    int b0 = blockIdx.x * NBC;
    int nb = (BB - b0 < NBC) ? (BB - b0) : NBC;

    if (t < HH)
        for (int j = 0; j < nb; ++j) sy[j * HH + t] = g_h0[(b0 + j) * HH + t];
    __syncthreads();

    for (int n = 0; n < SS; ++n) {
        int m1 = (n > 0) ? (n - 1) : 0;
        // k1 = f(y, m1)
        mlp_stage<HH, 0>(sy, h1_w, h1_b, sbA, sRed, nb, t);
        mlp_stage<WWID, 0>(sbA, h2_w, h2_b, sbB, sRed, nb, t);
        mlp_stage<WWID, 1>(sbB, vo_w, vo_b, sbA, sRed, nb, t);
        contract_stage(sbA, m1, b0, nb, sk1, sRed, t);
        if (t < HH)
            for (int j = 0; j < nb; ++j)
                sym[j * HH + t] = sy[j * HH + t] + sk1[j * HH + t];
        __syncthreads();
        // k2 = f(y + k1, n)
        mlp_stage<HH, 0>(sym, h1_w, h1_b, sbA, sRed, nb, t);
        mlp_stage<WWID, 0>(sbA, h2_w, h2_b, sbB, sRed, nb, t);
        mlp_stage<WWID, 1>(sbB, vo_w, vo_b, sbA, sRed, nb, t);
        contract_stage(sbA, n, b0, nb, sk2, sRed, t);
        if (t < HH) {
            for (int j = 0; j < nb; ++j) {
                float yn = sy[j * HH + t] + 0.5f * (sk1[j * HH + t] + sk2[j * HH + t]);
                sy[j * HH + t] = yn;
                if (write_feat)
                    out[(size_t)(b0 + j) * (SS + 1) * HH + (size_t)(n + 1) * HH + t] = yn;
                if (n == SS - 1 && last_off >= 0)
                    out[(size_t)last_off + (size_t)(b0 + j) * HH + t] = yn;
            }
        }
        __syncthreads();
    }
}

// ---------------- launch -------------------------------------------------------------
extern "C" void kernel_launch(void* const* d_in, const int* in_sizes, int n_in,
                              void* d_out, int out_size) {
    const float* logsig  = (const float*)d_in[1];
    const float* initial = (const float*)d_in[2];
    const float* in_w    = (const float*)d_in[3];
    const float* in_b    = (const float*)d_in[4];
    const float* h1_w    = (const float*)d_in[5];
    const float* h1_b    = (const float*)d_in[6];
    const float* h2_w    = (const float*)d_in[7];
    const float* h2_b    = (const float*)d_in[8];
    const float* vo_w    = (const float*)d_in[9];
    const float* vo_b    = (const float*)d_in[10];
    const float* ml_w    = (const float*)d_in[11];
    const float* ml_b    = (const float*)d_in[12];
    float* out = (float*)d_out;

    const long long feat_sz = (long long)BB * (SS + 1) * HH;   // 1,064,960
    const long long last_sz = (long long)BB * HH;              // 16,384
    int write_feat = (out_size >= feat_sz) ? 1 : 0;
    long long last_off = -1;
    if (out_size >= feat_sz + last_sz) last_off = feat_sz;      // full tuple output
    else if (!write_feat && out_size >= last_sz) last_off = 0;  // last-only fallback

    k_h0<<<BB, HH>>>(initial, in_w, in_b, out, write_feat);
    // coeffs^T : [136][8192] from logsig (stride 137, offset 1)
    k_transpose<<<dim3(5, (BB * SS) / 32), dim3(32, 8)>>>(logsig, BB * SS, DD, DD + 1, 1, 0);
    // ml_w^T   : [136][32768]
    k_transpose<<<dim3(5, (WWID * HH) / 32), dim3(32, 8)>>>(ml_w, WWID * HH, DD, DD, 0, 1);
    k_cbias<<<BB * SS, HH>>>(logsig, ml_b);
    k_gemmG<<<dim3((WWID * HH) / 128, (BB * SS) / 128), 256>>>();
    k_scan<<<NCTA, 256>>>(h1_w, h1_b, h2_w, h2_b, vo_w, vo_b, out, write_feat, last_off);
}

// round 3
// speedup vs baseline: 1.5631x; 1.5631x over previous
#include <cuda_runtime.h>
#include <cuda_bf16.h>
#include <cstdint>
#include <math.h>

#define BB   128
#define SS   64
#define HH   128
#define WWID 256
#define DD   136
#define DIN  64
#define KPM  144                 // K padded to multiple of 16
#define GM   (BB * SS)           // 8192
#define GN   (WWID * HH)         // 32768
#define NBC  3
#define NCTA ((BB + NBC - 1) / NBC)   // 43

// ---------------- device scratch ----------------
__device__ float g_G[(size_t)GM * GN];          // 1 GiB fp32
__device__ float g_cbias[GM * HH];
__device__ float g_h0[BB * HH];
__device__ __nv_bfloat16 g_Ahi[(size_t)GM * KPM];
__device__ __nv_bfloat16 g_Alo[(size_t)GM * KPM];
__device__ __nv_bfloat16 g_Bhi[(size_t)GN * KPM];
__device__ __nv_bfloat16 g_Blo[(size_t)GN * KPM];

// ---------------- helpers ----------------
__device__ __forceinline__ uint32_t s2u(const void* p) {
    uint32_t a;
    asm("{ .reg .u64 t; cvta.to.shared.u64 t, %1; cvt.u32.u64 %0, t; }" : "=r"(a) : "l"(p));
    return a;
}
__device__ __forceinline__ float2 fma2(float2 d, float2 a, float2 b) {
    union U { float2 f; unsigned long long u; };
    U ud, ua, ub; ud.f = d; ua.f = a; ub.f = b;
    asm("fma.rn.f32x2 %0, %1, %2, %0;" : "+l"(ud.u) : "l"(ua.u), "l"(ub.u));
    return ud.f;
}

// ---------------- h0 = initial @ in_w + in_b ----------------
__global__ void k_h0(const float* __restrict__ initial, const float* __restrict__ in_w,
                     const float* __restrict__ in_b, float* __restrict__ out, int write_feat) {
    int b = blockIdx.x, t = threadIdx.x;
    __shared__ float si[DIN];
    if (t < DIN) si[t] = initial[b * DIN + t];
    __syncthreads();
    float acc = in_b[t];
    #pragma unroll 8
    for (int k = 0; k < DIN; ++k) acc = fmaf(si[k], in_w[k * HH + t], acc);
    g_h0[b * HH + t] = acc;
    if (write_feat) out[(size_t)b * (SS + 1) * HH + t] = acc;
}

// ---------------- bf16 hi/lo splits (K padded to 144 with zeros) ----------------
__global__ void k_splitA(const float* __restrict__ logsig) {
    int i = blockIdx.x, c = threadIdx.x;   // 144 threads
    float v = (c < DD) ? logsig[(size_t)i * (DD + 1) + 1 + c] : 0.f;
    __nv_bfloat16 hi = __float2bfloat16(v);
    __nv_bfloat16 lo = __float2bfloat16(v - __bfloat162float(hi));
    g_Ahi[(size_t)i * KPM + c] = hi;
    g_Alo[(size_t)i * KPM + c] = lo;
}
__global__ void k_splitB(const float* __restrict__ ml_w) {
    int j = blockIdx.x, c = threadIdx.x;   // j = w*128 + h
    int w = j >> 7, h = j & 127;
    float v = (c < DD) ? ml_w[(size_t)w * (HH * DD) + h * DD + c] : 0.f;
    __nv_bfloat16 hi = __float2bfloat16(v);
    __nv_bfloat16 lo = __float2bfloat16(v - __bfloat162float(hi));
    g_Bhi[(size_t)j * KPM + c] = hi;
    g_Blo[(size_t)j * KPM + c] = lo;
}

// ---------------- cbias[i][h] = sum_d ml_b[h*136+d] * coeffs[i][d] ----------------
__global__ void k_cbias(const float* __restrict__ logsig, const float* __restrict__ ml_b) {
    extern __shared__ float s[];
    float* mlb  = s;                 // HH rows, stride 137 (conflict-free)
    float* coef = s + HH * 137;
    float* part = coef + 160;
    int t = threadIdx.x;             // 256 threads
    for (int idx = t; idx < HH * DD; idx += 256) {
        int h = idx / DD, d = idx - h * DD;
        mlb[h * 137 + d] = ml_b[idx];
    }
    int i0 = blockIdx.x * 16;
    for (int r = 0; r < 16; ++r) {
        int i = i0 + r;
        __syncthreads();
        if (t < DD) coef[t] = logsig[(size_t)i * (DD + 1) + 1 + t];
        __syncthreads();
        int h = t & 127, half = t >> 7;
        int d0 = half * 68;
        float acc = 0.f;
        #pragma unroll 4
        for (int d = 0; d < 68; ++d) acc = fmaf(coef[d0 + d], mlb[h * 137 + d0 + d], acc);
        part[t] = acc;
        __syncthreads();
        if (t < HH) g_cbias[(size_t)i * HH + t] = part[t] + part[t + 128];
    }
}

// ---------------- mma.sync bf16 3-pass GEMM: G[8192 x 32768] ----------------
#define SR 152                      // smem row stride in bf16 (304B: ldmatrix conflict-free)
#define SMEM_MMA (4 * 128 * SR * 2) // 155648 B

__device__ __forceinline__ void ldm_x4(uint32_t* r, uint32_t addr) {
    asm volatile("ldmatrix.sync.aligned.m8n8.x4.shared.b16 {%0,%1,%2,%3}, [%4];"
                 : "=r"(r[0]), "=r"(r[1]), "=r"(r[2]), "=r"(r[3]) : "r"(addr));
}
__device__ __forceinline__ void mma_bf16(float* c, const uint32_t* a, const uint32_t* b) {
    asm volatile(
        "mma.sync.aligned.m16n8k16.row.col.f32.bf16.bf16.f32 "
        "{%0,%1,%2,%3}, {%4,%5,%6,%7}, {%8,%9}, {%0,%1,%2,%3};"
        : "+f"(c[0]), "+f"(c[1]), "+f"(c[2]), "+f"(c[3])
        : "r"(a[0]), "r"(a[1]), "r"(a[2]), "r"(a[3]), "r"(b[0]), "r"(b[1]));
}

__global__ void __launch_bounds__(256, 1) k_gemm_mma() {
    extern __shared__ __nv_bfloat16 sm[];
    __nv_bfloat16* sAh = sm;
    __nv_bfloat16* sAl = sm + 128 * SR;
    __nv_bfloat16* sBh = sm + 2 * 128 * SR;
    __nv_bfloat16* sBl = sm + 3 * 128 * SR;

    int t = threadIdx.x, lane = t & 31;
    int wid = t >> 5, wm = wid >> 2, wn = wid & 3;
    int j0 = blockIdx.x << 7, i0 = blockIdx.y << 7;

    // ---- load all four 128 x 144 tiles into smem (uint4 = 8 bf16; 18 per src row, 19 per dst row)
    {
        const uint4* srcs[4] = {
            (const uint4*)(g_Ahi + (size_t)i0 * KPM), (const uint4*)(g_Alo + (size_t)i0 * KPM),
            (const uint4*)(g_Bhi + (size_t)j0 * KPM), (const uint4*)(g_Blo + (size_t)j0 * KPM) };
        uint4* dsts[4] = { (uint4*)sAh, (uint4*)sAl, (uint4*)sBh, (uint4*)sBl };
        #pragma unroll
        for (int arr = 0; arr < 4; ++arr) {
            const uint4* src = srcs[arr];
            uint4* dst = dsts[arr];
            #pragma unroll
            for (int rep = 0; rep < 9; ++rep) {
                int idx = rep * 256 + t;           // 2304 chunks
                int r = idx / 18, c = idx - r * 18;
                dst[r * 19 + c] = src[r * 18 + c];
            }
        }
    }
    __syncthreads();

    float acc[4][4][4];
    #pragma unroll
    for (int i = 0; i < 4; ++i)
        #pragma unroll
        for (int j = 0; j < 4; ++j)
            #pragma unroll
            for (int q = 0; q < 4; ++q) acc[i][j][q] = 0.f;

    // lane-relative element offsets (bf16 units)
    int arow = (lane & 7) + ((lane >> 3) & 1) * 8;
    int acol = (lane >> 4) * 8;
    int brow = (lane & 7) + ((lane >> 4) & 1) * 8;
    int bcol = ((lane >> 3) & 1) * 8;

    uint32_t aoff[4], boff[2];
    #pragma unroll
    for (int mf = 0; mf < 4; ++mf)
        aoff[mf] = (uint32_t)((wm * 64 + mf * 16 + arow) * SR + acol) * 2;
    #pragma unroll
    for (int nf = 0; nf < 2; ++nf)
        boff[nf] = (uint32_t)((wn * 32 + nf * 16 + brow) * SR + bcol) * 2;

    uint32_t baseA[3] = { s2u(sAh), s2u(sAh), s2u(sAl) };
    uint32_t baseB[3] = { s2u(sBh), s2u(sBl), s2u(sBh) };

    #pragma unroll 1
    for (int p = 0; p < 3; ++p) {
        uint32_t bA = baseA[p], bB = baseB[p];
        #pragma unroll 1
        for (int kc = 0; kc < KPM / 16; ++kc) {
            uint32_t koff = (uint32_t)kc * 32;   // 16 bf16 = 32 B
            uint32_t aR[4][4], bR[4][2];
            #pragma unroll
            for (int mf = 0; mf < 4; ++mf) ldm_x4(aR[mf], bA + aoff[mf] + koff);
            #pragma unroll
            for (int nf = 0; nf < 2; ++nf) {
                uint32_t r4[4];
                ldm_x4(r4, bB + boff[nf] + koff);
                bR[nf * 2][0] = r4[0]; bR[nf * 2][1] = r4[1];
                bR[nf * 2 + 1][0] = r4[2]; bR[nf * 2 + 1][1] = r4[3];
            }
            #pragma unroll
            for (int mf = 0; mf < 4; ++mf)
                #pragma unroll
                for (int nf = 0; nf < 4; ++nf)
                    mma_bf16(acc[mf][nf], aR[mf], bR[nf]);
        }
    }

    // ---- epilogue: fp32 direct to gmem
    int rbase = i0 + wm * 64 + (lane >> 2);
    int cbase = j0 + wn * 32 + (lane & 3) * 2;
    #pragma unroll
    for (int mf = 0; mf < 4; ++mf) {
        #pragma unroll
        for (int nf = 0; nf < 4; ++nf) {
            size_t r0 = (size_t)(rbase + mf * 16) * GN + cbase + nf * 8;
            size_t r1 = r0 + 8 * (size_t)GN;
            *(float2*)&g_G[r0] = make_float2(acc[mf][nf][0], acc[mf][nf][1]);
            *(float2*)&g_G[r1] = make_float2(acc[mf][nf][2], acc[mf][nf][3]);
        }
    }
}

// ---------------- scan kernel ----------------
template <int K, int ACT>
__device__ __forceinline__ void mlp_stage(const float* sIn, const float* __restrict__ Wg,
                                          const float* __restrict__ bias, float* sOut,
                                          float* sRed, int nb, int t) {
    const int Kc = K / 4;
    int kc = t >> 6, g = t & 63, n0 = g * 4;
    float2 axy[NBC], azw[NBC];
    #pragma unroll
    for (int j = 0; j < NBC; ++j) { axy[j] = make_float2(0.f, 0.f); azw[j] = make_float2(0.f, 0.f); }
    #pragma unroll 4
    for (int kk4 = 0; kk4 < Kc / 4; ++kk4) {
        int k = kc * Kc + kk4 * 4;
        float4 a4[NBC];
        #pragma unroll
        for (int j = 0; j < NBC; ++j)
            if (j < nb) a4[j] = *(const float4*)&sIn[j * K + k];
        #pragma unroll
        for (int u = 0; u < 4; ++u) {
            float4 w4 = *(const float4*)(Wg + (size_t)(k + u) * WWID + n0);
            float2 wxy = make_float2(w4.x, w4.y), wzw = make_float2(w4.z, w4.w);
            #pragma unroll
            for (int j = 0; j < NBC; ++j) {
                if (j < nb) {
                    const float* ap = (const float*)&a4[j];
                    float2 a2 = make_float2(ap[u], ap[u]);
                    axy[j] = fma2(axy[j], a2, wxy);
                    azw[j] = fma2(azw[j], a2, wzw);
                }
            }
        }
    }
    #pragma unroll
    for (int j = 0; j < NBC; ++j)
        if (j < nb)
            *(float4*)&sRed[(kc * NBC + j) * 256 + n0] =
                make_float4(axy[j].x, axy[j].y, azw[j].x, azw[j].y);
    __syncthreads();
    if (t < 64 * NBC) {
        int j = t >> 6, gg = t & 63, m0 = gg * 4;
        if (j < nb) {
            float4 s = make_float4(0.f, 0.f, 0.f, 0.f);
            #pragma unroll
            for (int q = 0; q < 4; ++q) {
                float4 p = *(const float4*)&sRed[(q * NBC + j) * 256 + m0];
                s.x += p.x; s.y += p.y; s.z += p.z; s.w += p.w;
            }
            float4 bb = __ldg((const float4*)(bias + m0));
            s.x += bb.x; s.y += bb.y; s.z += bb.z; s.w += bb.w;
            if (ACT == 0) {
                s.x = fmaxf(s.x, 0.f); s.y = fmaxf(s.y, 0.f);
                s.z = fmaxf(s.z, 0.f); s.w = fmaxf(s.w, 0.f);
            } else {
                s.x = tanhf(s.x); s.y = tanhf(s.y); s.z = tanhf(s.z); s.w = tanhf(s.w);
            }
            *(float4*)&sOut[j * 256 + m0] = s;
        }
    }
    __syncthreads();
}

__device__ __forceinline__ void contract_stage(const float* shv, int m, int b0, int nb,
                                               float* sK, float* sRed, int t) {
    int wq = t >> 5, hq = t & 31, h0 = hq * 4;
    float2 axy[NBC], azw[NBC];
    const float4* Gb[NBC];
    #pragma unroll
    for (int j = 0; j < NBC; ++j) {
        axy[j] = make_float2(0.f, 0.f); azw[j] = make_float2(0.f, 0.f);
        int b = (b0 + j < BB) ? (b0 + j) : (BB - 1);
        Gb[j] = (const float4*)(g_G + ((size_t)b * SS + m) * WWID * HH);
    }
    #pragma unroll 4
    for (int ww = 0; ww < 32; ++ww) {
        int w = wq * 32 + ww;
        #pragma unroll
        for (int j = 0; j < NBC; ++j) {
            if (j < nb) {
                float4 g4 = __ldg(&Gb[j][w * 32 + hq]);
                float a = shv[j * WWID + w];
                float2 a2 = make_float2(a, a);
                axy[j] = fma2(axy[j], a2, make_float2(g4.x, g4.y));
                azw[j] = fma2(azw[j], a2, make_float2(g4.z, g4.w));
            }
        }
    }
    #pragma unroll
    for (int j = 0; j < NBC; ++j)
        if (j < nb)
            *(float4*)&sRed[(wq * NBC + j) * 128 + h0] =
                make_float4(axy[j].x, axy[j].y, azw[j].x, azw[j].y);
    __syncthreads();
    if (t < HH) {
        #pragma unroll
        for (int j = 0; j < NBC; ++j) {
            if (j < nb) {
                float v = g_cbias[((size_t)(b0 + j) * SS + m) * HH + t];
                #pragma unroll
                for (int q = 0; q < 8; ++q) v += sRed[(q * NBC + j) * 128 + t];
                sK[j * HH + t] = v;
            }
        }
    }
    __syncthreads();
}

#define SCAN_SMEM ((32768 + 4 * (NBC * HH) + 2 * (NBC * WWID) + 4 * NBC * 256) * 4)

__global__ void __launch_bounds__(256, 1) k_scan(
        const float* __restrict__ h1_w, const float* __restrict__ h1_b,
        const float* __restrict__ h2_w, const float* __restrict__ h2_b,
        const float* __restrict__ vo_w, const float* __restrict__ vo_b,
        float* __restrict__ out, int write_feat, long long last_off) {
    extern __shared__ float ssm[];
    float* h1s  = ssm;
    float* sy   = ssm + 32768;
    float* sym  = sy  + NBC * HH;
    float* sk1  = sym + NBC * HH;
    float* sk2  = sk1 + NBC * HH;
    float* sbA  = sk2 + NBC * HH;
    float* sbB  = sbA + NBC * WWID;
    float* sRed = sbB + NBC * WWID;

    int t = threadIdx.x;
    int b0 = blockIdx.x * NBC;
    int nb = (BB - b0 < NBC) ? (BB - b0) : NBC;

    for (int idx = t; idx < (HH * WWID) / 4; idx += 256)
        ((float4*)h1s)[idx] = ((const float4*)h1_w)[idx];
    if (t < HH)
        for (int j = 0; j < nb; ++j) sy[j * HH + t] = g_h0[(b0 + j) * HH + t];
    __syncthreads();

    for (int n = 0; n < SS; ++n) {
        int m1 = (n > 0) ? (n - 1) : 0;
        mlp_stage<HH, 0>(sy, h1s, h1_b, sbA, sRed, nb, t);
        mlp_stage<WWID, 0>(sbA, h2_w, h2_b, sbB, sRed, nb, t);
        mlp_stage<WWID, 1>(sbB, vo_w, vo_b, sbA, sRed, nb, t);
        contract_stage(sbA, m1, b0, nb, sk1, sRed, t);
        if (t < HH)
            for (int j = 0; j < nb; ++j)
                sym[j * HH + t] = sy[j * HH + t] + sk1[j * HH + t];
        __syncthreads();
        mlp_stage<HH, 0>(sym, h1s, h1_b, sbA, sRed, nb, t);
        mlp_stage<WWID, 0>(sbA, h2_w, h2_b, sbB, sRed, nb, t);
        mlp_stage<WWID, 1>(sbB, vo_w, vo_b, sbA, sRed, nb, t);
        contract_stage(sbA, n, b0, nb, sk2, sRed, t);
        if (t < HH) {
            for (int j = 0; j < nb; ++j) {
                float yn = sy[j * HH + t] + 0.5f * (sk1[j * HH + t] + sk2[j * HH + t]);
                sy[j * HH + t] = yn;
                if (write_feat)
                    out[(size_t)(b0 + j) * (SS + 1) * HH + (size_t)(n + 1) * HH + t] = yn;
                if (n == SS - 1 && last_off >= 0)
                    out[(size_t)last_off + (size_t)(b0 + j) * HH + t] = yn;
            }
        }
        __syncthreads();
    }
}

// ---------------- launch ----------------
extern "C" void kernel_launch(void* const* d_in, const int* in_sizes, int n_in,
                              void* d_out, int out_size) {
    const float* logsig  = (const float*)d_in[1];
    const float* initial = (const float*)d_in[2];
    const float* in_w    = (const float*)d_in[3];
    const float* in_b    = (const float*)d_in[4];
    const float* h1_w    = (const float*)d_in[5];
    const float* h1_b    = (const float*)d_in[6];
    const float* h2_w    = (const float*)d_in[7];
    const float* h2_b    = (const float*)d_in[8];
    const float* vo_w    = (const float*)d_in[9];
    const float* vo_b    = (const float*)d_in[10];
    const float* ml_w    = (const float*)d_in[11];
    const float* ml_b    = (const float*)d_in[12];
    float* out = (float*)d_out;

    const long long feat_sz = (long long)BB * (SS + 1) * HH;
    const long long last_sz = (long long)BB * HH;
    int write_feat = (out_size >= feat_sz) ? 1 : 0;
    long long last_off = -1;
    if (out_size >= feat_sz + last_sz) last_off = feat_sz;
    else if (!write_feat && out_size >= last_sz) last_off = 0;

    const int cbias_smem = (HH * 137 + 160 + 256) * 4;
    cudaFuncSetAttribute(k_cbias,    cudaFuncAttributeMaxDynamicSharedMemorySize, cbias_smem);
    cudaFuncSetAttribute(k_gemm_mma, cudaFuncAttributeMaxDynamicSharedMemorySize, SMEM_MMA);
    cudaFuncSetAttribute(k_scan,     cudaFuncAttributeMaxDynamicSharedMemorySize, SCAN_SMEM);

    k_h0<<<BB, HH>>>(initial, in_w, in_b, out, write_feat);
    k_splitA<<<GM, KPM>>>(logsig);
    k_splitB<<<GN, KPM>>>(ml_w);
    k_cbias<<<GM / 16, 256, cbias_smem>>>(logsig, ml_b);
    k_gemm_mma<<<dim3(GN / 128, GM / 128), 256, SMEM_MMA>>>();
    k_scan<<<NCTA, 256, SCAN_SMEM>>>(h1_w, h1_b, h2_w, h2_b, vo_w, vo_b, out, write_feat, last_off);
}

// round 4
// speedup vs baseline: 2.0587x; 1.3171x over previous
#include <cuda_runtime.h>
#include <cuda_bf16.h>
#include <cuda_fp16.h>
#include <cstdint>
#include <math.h>

#define BB   128
#define SS   64
#define HH   128
#define WWID 256
#define DD   136
#define DIN  64
#define KPM  144
#define GM   (BB * SS)           // 8192
#define GN   (WWID * HH)         // 32768
#define CL   4                   // cluster size
#define RPC  4                   // batch rows per cluster
#define NCLUS (BB / RPC)         // 32
#define SCAN_CTAS (NCLUS * CL)   // 128

// ---------------- device scratch ----------------
__device__ __half g_Gh[(size_t)GM * GN];        // 512 MB fp16
__device__ float g_cbias[GM * HH];
__device__ float g_h0[BB * HH];
__device__ __nv_bfloat16 g_Ahi[(size_t)GM * KPM];
__device__ __nv_bfloat16 g_Alo[(size_t)GM * KPM];
__device__ __nv_bfloat16 g_Bhi[(size_t)GN * KPM];
__device__ __nv_bfloat16 g_Blo[(size_t)GN * KPM];

// ---------------- helpers ----------------
__device__ __forceinline__ uint32_t s2u(const void* p) {
    uint32_t a;
    asm("{ .reg .u64 t; cvta.to.shared.u64 t, %1; cvt.u32.u64 %0, t; }" : "=r"(a) : "l"(p));
    return a;
}
__device__ __forceinline__ float2 fma2(float2 d, float2 a, float2 b) {
    union U { float2 f; unsigned long long u; };
    U ud, ua, ub; ud.f = d; ua.f = a; ub.f = b;
    asm("fma.rn.f32x2 %0, %1, %2, %0;" : "+l"(ud.u) : "l"(ua.u), "l"(ub.u));
    return ud.f;
}
__device__ __forceinline__ void st_cluster_f32(uint32_t addr, uint32_t rank, float v) {
    asm volatile("{\n\t.reg .b32 ra;\n\tmapa.shared::cluster.u32 ra, %0, %1;\n\t"
                 "st.shared::cluster.f32 [ra], %2;\n\t}"
                 :: "r"(addr), "r"(rank), "f"(v) : "memory");
}
__device__ __forceinline__ uint32_t cl_rank() {
    uint32_t r; asm("mov.u32 %0, %%cluster_ctarank;" : "=r"(r)); return r;
}
#define CL_SYNC() do { \
    asm volatile("barrier.cluster.arrive.aligned;" ::: "memory"); \
    asm volatile("barrier.cluster.wait.aligned;" ::: "memory"); } while (0)

// ---------------- h0 ----------------
__global__ void k_h0(const float* __restrict__ initial, const float* __restrict__ in_w,
                     const float* __restrict__ in_b, float* __restrict__ out, int write_feat) {
    int b = blockIdx.x, t = threadIdx.x;
    __shared__ float si[DIN];
    if (t < DIN) si[t] = initial[b * DIN + t];
    __syncthreads();
    float acc = in_b[t];
    #pragma unroll 8
    for (int k = 0; k < DIN; ++k) acc = fmaf(si[k], in_w[k * HH + t], acc);
    g_h0[b * HH + t] = acc;
    if (write_feat) out[(size_t)b * (SS + 1) * HH + t] = acc;
}

// ---------------- bf16 hi/lo splits ----------------
__global__ void k_splitA(const float* __restrict__ logsig) {
    int i = blockIdx.x, c = threadIdx.x;
    float v = (c < DD) ? logsig[(size_t)i * (DD + 1) + 1 + c] : 0.f;
    __nv_bfloat16 hi = __float2bfloat16(v);
    __nv_bfloat16 lo = __float2bfloat16(v - __bfloat162float(hi));
    g_Ahi[(size_t)i * KPM + c] = hi;
    g_Alo[(size_t)i * KPM + c] = lo;
}
__global__ void k_splitB(const float* __restrict__ ml_w) {
    int j = blockIdx.x, c = threadIdx.x;
    int w = j >> 7, h = j & 127;
    float v = (c < DD) ? ml_w[(size_t)w * (HH * DD) + h * DD + c] : 0.f;
    __nv_bfloat16 hi = __float2bfloat16(v);
    __nv_bfloat16 lo = __float2bfloat16(v - __bfloat162float(hi));
    g_Bhi[(size_t)j * KPM + c] = hi;
    g_Blo[(size_t)j * KPM + c] = lo;
}

// ---------------- cbias ----------------
__global__ void k_cbias(const float* __restrict__ logsig, const float* __restrict__ ml_b) {
    extern __shared__ float s[];
    float* mlb  = s;
    float* coef = s + HH * 137;
    float* part = coef + 160;
    int t = threadIdx.x;
    for (int idx = t; idx < HH * DD; idx += 256) {
        int h = idx / DD, d = idx - h * DD;
        mlb[h * 137 + d] = ml_b[idx];
    }
    int i0 = blockIdx.x * 16;
    for (int r = 0; r < 16; ++r) {
        int i = i0 + r;
        __syncthreads();
        if (t < DD) coef[t] = logsig[(size_t)i * (DD + 1) + 1 + t];
        __syncthreads();
        int h = t & 127, half = t >> 7;
        int d0 = half * 68;
        float acc = 0.f;
        #pragma unroll 4
        for (int d = 0; d < 68; ++d) acc = fmaf(coef[d0 + d], mlb[h * 137 + d0 + d], acc);
        part[t] = acc;
        __syncthreads();
        if (t < HH) g_cbias[(size_t)i * HH + t] = part[t] + part[t + 128];
    }
}

// ---------------- mma.sync bf16 3-pass GEMM -> fp16 G ----------------
#define SR 152
#define SMEM_MMA (4 * 128 * SR * 2)

__device__ __forceinline__ void ldm_x4(uint32_t* r, uint32_t addr) {
    asm volatile("ldmatrix.sync.aligned.m8n8.x4.shared.b16 {%0,%1,%2,%3}, [%4];"
                 : "=r"(r[0]), "=r"(r[1]), "=r"(r[2]), "=r"(r[3]) : "r"(addr));
}
__device__ __forceinline__ void mma_bf16(float* c, const uint32_t* a, const uint32_t* b) {
    asm volatile(
        "mma.sync.aligned.m16n8k16.row.col.f32.bf16.bf16.f32 "
        "{%0,%1,%2,%3}, {%4,%5,%6,%7}, {%8,%9}, {%0,%1,%2,%3};"
        : "+f"(c[0]), "+f"(c[1]), "+f"(c[2]), "+f"(c[3])
        : "r"(a[0]), "r"(a[1]), "r"(a[2]), "r"(a[3]), "r"(b[0]), "r"(b[1]));
}

__global__ void __launch_bounds__(256, 1) k_gemm_mma() {
    extern __shared__ __nv_bfloat16 sm[];
    __nv_bfloat16* sAh = sm;
    __nv_bfloat16* sAl = sm + 128 * SR;
    __nv_bfloat16* sBh = sm + 2 * 128 * SR;
    __nv_bfloat16* sBl = sm + 3 * 128 * SR;

    int t = threadIdx.x, lane = t & 31;
    int wid = t >> 5, wm = wid >> 2, wn = wid & 3;
    int j0 = blockIdx.x << 7, i0 = blockIdx.y << 7;

    {
        const uint4* srcs[4] = {
            (const uint4*)(g_Ahi + (size_t)i0 * KPM), (const uint4*)(g_Alo + (size_t)i0 * KPM),
            (const uint4*)(g_Bhi + (size_t)j0 * KPM), (const uint4*)(g_Blo + (size_t)j0 * KPM) };
        uint4* dsts[4] = { (uint4*)sAh, (uint4*)sAl, (uint4*)sBh, (uint4*)sBl };
        #pragma unroll
        for (int arr = 0; arr < 4; ++arr) {
            const uint4* src = srcs[arr];
            uint4* dst = dsts[arr];
            #pragma unroll
            for (int rep = 0; rep < 9; ++rep) {
                int idx = rep * 256 + t;
                int r = idx / 18, c = idx - r * 18;
                dst[r * 19 + c] = src[r * 18 + c];
            }
        }
    }
    __syncthreads();

    float acc[4][4][4];
    #pragma unroll
    for (int i = 0; i < 4; ++i)
        #pragma unroll
        for (int j = 0; j < 4; ++j)
            #pragma unroll
            for (int q = 0; q < 4; ++q) acc[i][j][q] = 0.f;

    int arow = (lane & 7) + ((lane >> 3) & 1) * 8;
    int acol = (lane >> 4) * 8;
    int brow = (lane & 7) + ((lane >> 4) & 1) * 8;
    int bcol = ((lane >> 3) & 1) * 8;

    uint32_t aoff[4], boff[2];
    #pragma unroll
    for (int mf = 0; mf < 4; ++mf)
        aoff[mf] = (uint32_t)((wm * 64 + mf * 16 + arow) * SR + acol) * 2;
    #pragma unroll
    for (int nf = 0; nf < 2; ++nf)
        boff[nf] = (uint32_t)((wn * 32 + nf * 16 + brow) * SR + bcol) * 2;

    uint32_t baseA[3] = { s2u(sAh), s2u(sAh), s2u(sAl) };
    uint32_t baseB[3] = { s2u(sBh), s2u(sBl), s2u(sBh) };

    #pragma unroll 1
    for (int p = 0; p < 3; ++p) {
        uint32_t bA = baseA[p], bB = baseB[p];
        #pragma unroll 1
        for (int kc = 0; kc < KPM / 16; ++kc) {
            uint32_t koff = (uint32_t)kc * 32;
            uint32_t aR[4][4], bR[4][2];
            #pragma unroll
            for (int mf = 0; mf < 4; ++mf) ldm_x4(aR[mf], bA + aoff[mf] + koff);
            #pragma unroll
            for (int nf = 0; nf < 2; ++nf) {
                uint32_t r4[4];
                ldm_x4(r4, bB + boff[nf] + koff);
                bR[nf * 2][0] = r4[0]; bR[nf * 2][1] = r4[1];
                bR[nf * 2 + 1][0] = r4[2]; bR[nf * 2 + 1][1] = r4[3];
            }
            #pragma unroll
            for (int mf = 0; mf < 4; ++mf)
                #pragma unroll
                for (int nf = 0; nf < 4; ++nf)
                    mma_bf16(acc[mf][nf], aR[mf], bR[nf]);
        }
    }

    // epilogue: fp16
    int rbase = i0 + wm * 64 + (lane >> 2);
    int cbase = j0 + wn * 32 + (lane & 3) * 2;
    #pragma unroll
    for (int mf = 0; mf < 4; ++mf) {
        #pragma unroll
        for (int nf = 0; nf < 4; ++nf) {
            size_t r0 = (size_t)(rbase + mf * 16) * GN + cbase + nf * 8;
            size_t r1 = r0 + 8 * (size_t)GN;
            *(__half2*)&g_Gh[r0] = __floats2half2_rn(acc[mf][nf][0], acc[mf][nf][1]);
            *(__half2*)&g_Gh[r1] = __floats2half2_rn(acc[mf][nf][2], acc[mf][nf][3]);
        }
    }
}

// ---------------- cluster-4 scan ----------------
// smem layout in floats:
#define OFF_W1  0              // [128][64]
#define OFF_W2  8192           // [256][64]
#define OFF_WV  24576          // [256][64]
#define OFF_B1  40960
#define OFF_B2  41024
#define OFF_BV  41088
#define OFF_SY  41152          // [128][4]
#define OFF_SYM 41664
#define OFF_SK1 42176
#define OFF_SK2 42688
#define OFF_A   43200          // [256][4]
#define OFF_B2F 44224          // [256][4]
#define OFF_RED 45248          // 2048
#define SCAN_FLOATS 47296
#define SCAN_SMEM (SCAN_FLOATS * 4)

// out[n] = act(bias[n] + sum_k in[k] * W[k][n]); each CTA computes n-chunk [64r,64r+64)
template <int K, int ACT>
__device__ __forceinline__ void mlp_stage(const float* __restrict__ sIn,
                                          const float* __restrict__ W,
                                          const float* __restrict__ bias,
                                          float* sRed, uint32_t outAddr,
                                          int r, int t) {
    const int Kc = K / 4;
    int kc = t >> 6, n = t & 63;
    float2 a01 = make_float2(0.f, 0.f), a23 = make_float2(0.f, 0.f);
    const float* Wp = W + n;
    #pragma unroll 8
    for (int kk = 0; kk < Kc; ++kk) {
        int k = kc * Kc + kk;
        float w = Wp[k * 64];
        float4 a = *(const float4*)&sIn[k * 4];
        float2 w2 = make_float2(w, w);
        a01 = fma2(a01, make_float2(a.x, a.y), w2);
        a23 = fma2(a23, make_float2(a.z, a.w), w2);
    }
    *(float4*)&sRed[t * 4] = make_float4(a01.x, a01.y, a23.x, a23.y);
    __syncthreads();
    {
        int n2 = t & 63, j = t >> 6;
        float v = sRed[(0 * 64 + n2) * 4 + j] + sRed[(1 * 64 + n2) * 4 + j]
                + sRed[(2 * 64 + n2) * 4 + j] + sRed[(3 * 64 + n2) * 4 + j];
        v += bias[n2];
        if (ACT == 0) v = fmaxf(v, 0.f); else v = tanhf(v);
        uint32_t addr = outAddr + (uint32_t)(((64 * r + n2) << 2) + j) * 4u;
        #pragma unroll
        for (int p = 0; p < CL; ++p) st_cluster_f32(addr, (uint32_t)p, v);
    }
    CL_SYNC();
}

// k-chunk [32r,32r+32): sK[h][j] = cbias + sum_w v[w][j] * G[b_j,m][w][h]
__device__ __forceinline__ void contract_stage(const float* __restrict__ sV,
                                               int m, int b0, int r,
                                               float* sRed, uint32_t kAddr,
                                               const float* __restrict__ cbias,
                                               int t) {
    int wg = t >> 4, hp = t & 15;     // 16 w-groups x 16 h-pairs
    // prefetch cbias for reduce phase
    float cb = 0.f;
    if (t < 128) {
        int j = t & 3, hh = t >> 2;
        cb = cbias[((size_t)(b0 + j) * SS + m) * HH + 32 * r + hh];
    }
    const __half2* Gp[RPC];
    #pragma unroll
    for (int j = 0; j < RPC; ++j)
        Gp[j] = (const __half2*)(g_Gh + ((size_t)(b0 + j) * SS + m) * GN) + 16 * r + hp;
    float2 acc[RPC];
    #pragma unroll
    for (int j = 0; j < RPC; ++j) acc[j] = make_float2(0.f, 0.f);
    #pragma unroll 4
    for (int ww = 0; ww < 16; ++ww) {
        int w = wg * 16 + ww;
        float4 v4 = *(const float4*)&sV[w * 4];
        const float* vp = (const float*)&v4;
        #pragma unroll
        for (int j = 0; j < RPC; ++j) {
            float2 g = __half22float2(Gp[j][(size_t)w * 64]);
            acc[j] = fma2(acc[j], make_float2(vp[j], vp[j]), g);
        }
    }
    #pragma unroll
    for (int j = 0; j < RPC; ++j) {
        sRed[wg * 128 + (2 * hp) * 4 + j]     = acc[j].x;
        sRed[wg * 128 + (2 * hp + 1) * 4 + j] = acc[j].y;
    }
    __syncthreads();
    if (t < 128) {
        int j = t & 3, hh = t >> 2;
        float v = cb;
        #pragma unroll
        for (int q = 0; q < 16; ++q) v += sRed[q * 128 + hh * 4 + j];
        uint32_t addr = kAddr + (uint32_t)(((32 * r + hh) << 2) + j) * 4u;
        #pragma unroll
        for (int p = 0; p < CL; ++p) st_cluster_f32(addr, (uint32_t)p, v);
    }
    CL_SYNC();
}

__global__ void __launch_bounds__(256, 1) __cluster_dims__(CL, 1, 1)
k_scan(const float* __restrict__ h1_w, const float* __restrict__ h1_b,
       const float* __restrict__ h2_w, const float* __restrict__ h2_b,
       const float* __restrict__ vo_w, const float* __restrict__ vo_b,
       float* __restrict__ out, int write_feat, long long last_off) {
    extern __shared__ float ss[];
    float* w1s = ss + OFF_W1;
    float* w2s = ss + OFF_W2;
    float* wvs = ss + OFF_WV;
    float* b1s = ss + OFF_B1;
    float* b2s = ss + OFF_B2;
    float* bvs = ss + OFF_BV;
    float* sy  = ss + OFF_SY;
    float* sym = ss + OFF_SYM;
    float* sk1 = ss + OFF_SK1;
    float* sk2 = ss + OFF_SK2;
    float* sbA = ss + OFF_A;
    float* sbB = ss + OFF_B2F;
    float* sRed = ss + OFF_RED;

    int t = threadIdx.x;
    int r = (int)cl_rank();
    int b0 = (blockIdx.x >> 2) * RPC;

    uint32_t aA  = s2u(sbA), aB = s2u(sbB);
    uint32_t aK1 = s2u(sk1), aK2 = s2u(sk2);

    // load weight slices (output-neuron split): W[k][64r + n]
    for (int idx = t; idx < HH * 64; idx += 256) {
        int k = idx >> 6, n = idx & 63;
        w1s[idx] = h1_w[k * WWID + 64 * r + n];
    }
    for (int idx = t; idx < WWID * 64; idx += 256) {
        int k = idx >> 6, n = idx & 63;
        w2s[idx] = h2_w[k * WWID + 64 * r + n];
        wvs[idx] = vo_w[k * WWID + 64 * r + n];
    }
    if (t < 64) {
        b1s[t] = h1_b[64 * r + t];
        b2s[t] = h2_b[64 * r + t];
        bvs[t] = vo_b[64 * r + t];
    }
    // load y0 (interleaved [h][4])
    for (int idx = t; idx < HH * RPC; idx += 256) {
        int h = idx >> 2, j = idx & 3;
        sy[idx] = g_h0[(b0 + j) * HH + h];
    }
    __syncthreads();

    for (int n = 0; n < SS; ++n) {
        int m1 = (n > 0) ? (n - 1) : 0;
        // k1 = f(y, m1)
        mlp_stage<HH, 0>(sy, w1s, b1s, sRed, aA, r, t);
        mlp_stage<WWID, 0>(sbA, w2s, b2s, sRed, aB, r, t);
        mlp_stage<WWID, 1>(sbB, wvs, bvs, sRed, aA, r, t);
        contract_stage(sbA, m1, b0, r, sRed, aK1, g_cbias, t);
        // sym = y + k1 (replicated everywhere)
        {
            int i0 = t, i1 = t + 256;
            sym[i0] = sy[i0] + sk1[i0];
            sym[i1] = sy[i1] + sk1[i1];
        }
        __syncthreads();
        // k2 = f(sym, n)
        mlp_stage<HH, 0>(sym, w1s, b1s, sRed, aA, r, t);
        mlp_stage<WWID, 0>(sbA, w2s, b2s, sRed, aB, r, t);
        mlp_stage<WWID, 1>(sbB, wvs, bvs, sRed, aA, r, t);
        contract_stage(sbA, n, b0, r, sRed, aK2, g_cbias, t);
        // y update + output
        {
            #pragma unroll
            for (int u = 0; u < 2; ++u) {
                int v = t + u * 256;
                int h = v >> 2, j = v & 3;
                float yn = sy[v] + 0.5f * (sk1[v] + sk2[v]);
                sy[v] = yn;
                if (write_feat)
                    out[(size_t)(b0 + j) * (SS + 1) * HH + (size_t)(n + 1) * HH + h] = yn;
                if (n == SS - 1 && last_off >= 0)
                    out[(size_t)last_off + (size_t)(b0 + j) * HH + h] = yn;
            }
        }
        __syncthreads();
    }
}

// ---------------- launch ----------------
extern "C" void kernel_launch(void* const* d_in, const int* in_sizes, int n_in,
                              void* d_out, int out_size) {
    const float* logsig  = (const float*)d_in[1];
    const float* initial = (const float*)d_in[2];
    const float* in_w    = (const float*)d_in[3];
    const float* in_b    = (const float*)d_in[4];
    const float* h1_w    = (const float*)d_in[5];
    const float* h1_b    = (const float*)d_in[6];
    const float* h2_w    = (const float*)d_in[7];
    const float* h2_b    = (const float*)d_in[8];
    const float* vo_w    = (const float*)d_in[9];
    const float* vo_b    = (const float*)d_in[10];
    const float* ml_w    = (const float*)d_in[11];
    const float* ml_b    = (const float*)d_in[12];
    float* out = (float*)d_out;

    const long long feat_sz = (long long)BB * (SS + 1) * HH;
    const long long last_sz = (long long)BB * HH;
    int write_feat = (out_size >= feat_sz) ? 1 : 0;
    long long last_off = -1;
    if (out_size >= feat_sz + last_sz) last_off = feat_sz;
    else if (!write_feat && out_size >= last_sz) last_off = 0;

    const int cbias_smem = (HH * 137 + 160 + 256) * 4;
    cudaFuncSetAttribute(k_cbias,    cudaFuncAttributeMaxDynamicSharedMemorySize, cbias_smem);
    cudaFuncSetAttribute(k_gemm_mma, cudaFuncAttributeMaxDynamicSharedMemorySize, SMEM_MMA);
    cudaFuncSetAttribute(k_scan,     cudaFuncAttributeMaxDynamicSharedMemorySize, SCAN_SMEM);

    k_h0<<<BB, HH>>>(initial, in_w, in_b, out, write_feat);
    k_splitA<<<GM, KPM>>>(logsig);
    k_splitB<<<GN, KPM>>>(ml_w);
    k_cbias<<<GM / 16, 256, cbias_smem>>>(logsig, ml_b);
    k_gemm_mma<<<dim3(GN / 128, GM / 128), 256, SMEM_MMA>>>();
    k_scan<<<SCAN_CTAS, 256, SCAN_SMEM>>>(h1_w, h1_b, h2_w, h2_b, vo_w, vo_b,
                                          out, write_feat, last_off);
}